// round 1
// baseline (speedup 1.0000x reference)
#include <cuda_runtime.h>
#include <math.h>

#define NIN     12
#define NC      16
#define HID     512
#define KBINS   8
#define BVAL    3.0f
#define LLAYERS 8
#define D_HALF  6
#define DIN     22      // D_HALF + NC
#define DOUT    138     // (3*K-1)*(NIN-D_HALF)
#define SPP     23      // 3*K-1 params per dim
#define TM      16      // rows per CTA
#define NT      512     // threads per CTA

__device__ __forceinline__ float eluf(float v) {
    return v > 0.0f ? v : expm1f(v);
}

__device__ __forceinline__ float softplusf(float v) {
    return v > 20.0f ? v : log1pf(expf(v));
}

// GEMM: h_in[TM][HID] @ W[HID][HID] + b -> elu -> h (in place).
// Mapping: 512 threads; jp = tid&255 -> column pair (2*jp, 2*jp+1);
// rh = tid>>8 -> row half (8 rows each).
__device__ __forceinline__ void gemm_hid(const float* __restrict__ W,
                                         const float* __restrict__ bb,
                                         float (*h)[HID], int tid)
{
    const int jp = tid & 255;
    const int rh = tid >> 8;
    const int j0 = jp * 2;
    const int rb = rh * 8;
    float a0[8], a1[8];
#pragma unroll
    for (int m = 0; m < 8; m++) { a0[m] = 0.0f; a1[m] = 0.0f; }
    for (int k = 0; k < HID; k += 4) {
        float2 wA = *(const float2*)(W + (size_t)(k + 0) * HID + j0);
        float2 wB = *(const float2*)(W + (size_t)(k + 1) * HID + j0);
        float2 wC = *(const float2*)(W + (size_t)(k + 2) * HID + j0);
        float2 wD = *(const float2*)(W + (size_t)(k + 3) * HID + j0);
#pragma unroll
        for (int m = 0; m < 8; m++) {
            float4 hv = *(const float4*)&h[rb + m][k];
            a0[m] = fmaf(hv.x, wA.x, a0[m]); a1[m] = fmaf(hv.x, wA.y, a1[m]);
            a0[m] = fmaf(hv.y, wB.x, a0[m]); a1[m] = fmaf(hv.y, wB.y, a1[m]);
            a0[m] = fmaf(hv.z, wC.x, a0[m]); a1[m] = fmaf(hv.z, wC.y, a1[m]);
            a0[m] = fmaf(hv.w, wD.x, a0[m]); a1[m] = fmaf(hv.w, wD.y, a1[m]);
        }
    }
    float bx = bb[j0], by = bb[j0 + 1];
    __syncthreads();   // all reads of h complete before in-place overwrite
#pragma unroll
    for (int m = 0; m < 8; m++) {
        float2 o;
        o.x = eluf(a0[m] + bx);
        o.y = eluf(a1[m] + by);
        *(float2*)&h[rb + m][j0] = o;
    }
    __syncthreads();
}

__global__ __launch_bounds__(NT) void flow_kernel(
    const float* __restrict__ z,  const float* __restrict__ c,
    const float* __restrict__ W0, const float* __restrict__ b0,
    const float* __restrict__ W1, const float* __restrict__ b1,
    const float* __restrict__ W2, const float* __restrict__ b2,
    const float* __restrict__ W3, const float* __restrict__ b3,
    const int*   __restrict__ perms,
    float* __restrict__ out, int n)
{
    __shared__ float h_s[TM][HID];          // 32 KB activation buffer
    __shared__ float out_s[TM][DOUT + 2];   // spline params
    __shared__ float inp_s[TM][DIN];
    __shared__ float x_s[TM][NIN];
    __shared__ float xt_s[TM][NIN];
    __shared__ float c_s[TM][NC];
    __shared__ float ld_s[TM];
    __shared__ float lad_s[TM][D_HALF];
    __shared__ int   perm_s[(LLAYERS - 1) * NIN];

    const int tid  = threadIdx.x;
    const int row0 = blockIdx.x * TM;

    for (int i = tid; i < TM * NIN; i += NT) x_s[i / NIN][i % NIN] = z[(size_t)row0 * NIN + i];
    for (int i = tid; i < TM * NC;  i += NT) c_s[i / NC][i % NC]   = c[(size_t)row0 * NC + i];
    if (tid < TM) ld_s[tid] = 0.0f;
    if (tid < (LLAYERS - 1) * NIN) perm_s[tid] = perms[tid];
    __syncthreads();

    for (int layer = 0; layer < LLAYERS; layer++) {
        // ---- build inp = concat(x1, c) ----
        if (tid < TM * DIN) {
            int m = tid / DIN, k = tid % DIN;
            inp_s[m][k] = (k < D_HALF) ? x_s[m][k] : c_s[m][k - D_HALF];
        }
        __syncthreads();

        // ---- GEMM0: inp[TM][22] @ W0 -> elu -> h_s ----
        {
            const float* W  = W0 + (size_t)layer * DIN * HID;
            const float* bb = b0 + (size_t)layer * HID;
            const int jp = tid & 255;
            const int rh = tid >> 8;
            const int j0 = jp * 2;
            const int rb = rh * 8;
            float a0[8], a1[8];
#pragma unroll
            for (int m = 0; m < 8; m++) { a0[m] = 0.0f; a1[m] = 0.0f; }
            for (int k = 0; k < DIN; k++) {
                float2 w = *(const float2*)(W + (size_t)k * HID + j0);
#pragma unroll
                for (int m = 0; m < 8; m++) {
                    float hv = inp_s[rb + m][k];
                    a0[m] = fmaf(hv, w.x, a0[m]);
                    a1[m] = fmaf(hv, w.y, a1[m]);
                }
            }
            float bx = bb[j0], by = bb[j0 + 1];
#pragma unroll
            for (int m = 0; m < 8; m++) {
                float2 o;
                o.x = eluf(a0[m] + bx);
                o.y = eluf(a1[m] + by);
                *(float2*)&h_s[rb + m][j0] = o;
            }
            __syncthreads();
        }

        // ---- GEMM1, GEMM2: 512x512, in-place ----
        gemm_hid(W1 + (size_t)layer * HID * HID, b1 + (size_t)layer * HID, h_s, tid);
        gemm_hid(W2 + (size_t)layer * HID * HID, b2 + (size_t)layer * HID, h_s, tid);

        // ---- GEMM3: h[TM][512] @ W3[512][138] + b3 -> out_s (no activation) ----
        {
            const float* W  = W3 + (size_t)layer * HID * DOUT;
            const float* bb = b3 + (size_t)layer * DOUT;
            const int jl = tid & 127;
            const int rg = tid >> 7;          // 0..3 -> rows rg*4..rg*4+3
            const bool has2 = jl < (DOUT - 128); // 10 extra columns
            float a[4], a2[4];
#pragma unroll
            for (int m = 0; m < 4; m++) { a[m] = 0.0f; a2[m] = 0.0f; }
            for (int k = 0; k < HID; k++) {
                float w  = W[(size_t)k * DOUT + jl];
                float w2 = has2 ? W[(size_t)k * DOUT + 128 + jl] : 0.0f;
#pragma unroll
                for (int m = 0; m < 4; m++) {
                    float hv = h_s[rg * 4 + m][k];
                    a[m]  = fmaf(hv, w,  a[m]);
                    a2[m] = fmaf(hv, w2, a2[m]);
                }
            }
            float bx  = bb[jl];
            float bx2 = has2 ? bb[128 + jl] : 0.0f;
#pragma unroll
            for (int m = 0; m < 4; m++) {
                out_s[rg * 4 + m][jl] = a[m] + bx;
                if (has2) out_s[rg * 4 + m][128 + jl] = a2[m] + bx2;
            }
            __syncthreads();
        }

        // ---- RQ spline: one thread per (row, dim) ----
        if (tid < TM * D_HALF) {
            const int m = tid / D_HALF, d = tid % D_HALF;
            const float* p = &out_s[m][d * SPP];

            // widths softmax -> knot x positions
            float e[KBINS];
            float mx = p[0];
#pragma unroll
            for (int i = 1; i < KBINS; i++) mx = fmaxf(mx, p[i]);
            float s = 0.0f;
#pragma unroll
            for (int i = 0; i < KBINS; i++) { e[i] = expf(p[i] - mx); s += e[i]; }
            float inv = 1.0f / s;
            float cw[KBINS + 1];
            cw[0] = -BVAL;
            {
                float run = 0.0f;
#pragma unroll
                for (int i = 0; i < KBINS - 1; i++) {
                    run += 0.001f + 0.992f * e[i] * inv;
                    cw[i + 1] = 2.0f * BVAL * run - BVAL;
                }
            }
            cw[KBINS] = BVAL;

            // heights softmax -> knot y positions
            mx = p[KBINS];
#pragma unroll
            for (int i = 1; i < KBINS; i++) mx = fmaxf(mx, p[KBINS + i]);
            s = 0.0f;
#pragma unroll
            for (int i = 0; i < KBINS; i++) { e[i] = expf(p[KBINS + i] - mx); s += e[i]; }
            inv = 1.0f / s;
            float ch[KBINS + 1];
            ch[0] = -BVAL;
            {
                float run = 0.0f;
#pragma unroll
                for (int i = 0; i < KBINS - 1; i++) {
                    run += 0.001f + 0.992f * e[i] * inv;
                    ch[i + 1] = 2.0f * BVAL * run - BVAL;
                }
            }
            ch[KBINS] = BVAL;

            // derivatives (edges exactly 1: MIN_D + softplus(DERIV_CONST) == 1)
            float dv[KBINS + 1];
            dv[0] = 1.0f; dv[KBINS] = 1.0f;
#pragma unroll
            for (int i = 1; i < KBINS; i++)
                dv[i] = 0.001f + softplusf(p[2 * KBINS + i - 1]);

            float x  = x_s[m][D_HALF + d];
            float xc = fminf(fmaxf(x, -BVAL), BVAL);
            int idx = 0;
#pragma unroll
            for (int i = 1; i < KBINS; i++) idx += (xc >= cw[i]) ? 1 : 0;

            float icw = cw[idx], iw = cw[idx + 1] - cw[idx];
            float ich = ch[idx], ih = ch[idx + 1] - ch[idx];
            float delta = ih / iw;
            float d0 = dv[idx], d1 = dv[idx + 1];
            float th  = (xc - icw) / iw;
            float t1m = th * (1.0f - th);
            float num = ih * (delta * th * th + d0 * t1m);
            float den = delta + (d0 + d1 - 2.0f * delta) * t1m;
            float o = ich + num / den;
            float omt = 1.0f - th;
            float dnum = delta * delta * (d1 * th * th + 2.0f * delta * t1m + d0 * omt * omt);
            float lad = logf(dnum) - 2.0f * logf(den);
            bool inside = (x >= -BVAL) && (x <= BVAL);
            x_s[m][D_HALF + d] = inside ? o : x;
            lad_s[m][d] = inside ? lad : 0.0f;
        }
        __syncthreads();

        // deterministic log-det reduction
        if (tid < TM) {
            float acc = ld_s[tid];
#pragma unroll
            for (int d = 0; d < D_HALF; d++) acc += lad_s[tid][d];
            ld_s[tid] = acc;
        }

        // ---- permutation ----
        if (layer < LLAYERS - 1) {
            if (tid < TM * NIN) {
                int m = tid / NIN, j = tid % NIN;
                xt_s[m][j] = x_s[m][perm_s[layer * NIN + j]];
            }
            __syncthreads();
            if (tid < TM * NIN) {
                int m = tid / NIN, j = tid % NIN;
                x_s[m][j] = xt_s[m][j];
            }
        }
        __syncthreads();
    }

    // ---- write outputs: x [N,12] then total_ld [N] ----
    for (int i = tid; i < TM * NIN; i += NT)
        out[(size_t)row0 * NIN + i] = x_s[i / NIN][i % NIN];
    if (tid < TM)
        out[(size_t)n * NIN + row0 + tid] = ld_s[tid];
}

extern "C" void kernel_launch(void* const* d_in, const int* in_sizes, int n_in,
                              void* d_out, int out_size)
{
    const float* z     = (const float*)d_in[0];
    const float* c     = (const float*)d_in[1];
    const float* W0    = (const float*)d_in[2];
    const float* b0    = (const float*)d_in[3];
    const float* W1    = (const float*)d_in[4];
    const float* b1    = (const float*)d_in[5];
    const float* W2    = (const float*)d_in[6];
    const float* b2    = (const float*)d_in[7];
    const float* W3    = (const float*)d_in[8];
    const float* b3    = (const float*)d_in[9];
    const int*   perms = (const int*)d_in[10];

    int n = in_sizes[0] / NIN;
    int grid = (n + TM - 1) / TM;
    flow_kernel<<<grid, NT>>>(z, c, W0, b0, W1, b1, W2, b2, W3, b3, perms,
                              (float*)d_out, n);
}